// round 16
// baseline (speedup 1.0000x reference)
#include <cuda_runtime.h>
#include <math.h>

#define Bb 16
#define Ss 512
#define Tt 512
#define Dd 512
#define Rr 8
#define NEG_BIG (-1e10f)
#define LOG2E 1.4426950408889634f
#define NNODE 64
#define NBLK 256

typedef unsigned long long u64;

// scratch (device globals; no allocation allowed)
__device__ float    g_src_wt[Bb * Rr * Ss];    // [b,r,s]
__device__ float    g_tar_wt[Bb * Rr * Tt];    // [b,r,t]
__device__ float    g_tab[Bb * Rr * NNODE];    // c(a) tables
__device__ float2   g_meta[Bb * Rr];           // (g0, 1/h) per (b,r)
__device__ unsigned g_bar = 0;                 // monotonic grid-barrier ticket

__device__ __forceinline__ float ex2(float x) {
    float y;
    asm("ex2.approx.f32 %0, %1;" : "=f"(y) : "f"(x));
    return y;
}
__device__ __forceinline__ u64 pk(float lo, float hi) {
    u64 d; asm("mov.b64 %0, {%1, %2};" : "=l"(d) : "f"(lo), "f"(hi)); return d;
}
__device__ __forceinline__ void upk(u64 p, float& lo, float& hi) {
    asm("mov.b64 {%0, %1}, %2;" : "=f"(lo), "=f"(hi) : "l"(p));
}
__device__ __forceinline__ u64 ffma2(u64 a, u64 b, u64 c) {
    u64 d; asm("fma.rn.f32x2 %0, %1, %2, %3;" : "=l"(d) : "l"(a), "l"(b), "l"(c)); return d;
}

// ---------------------------------------------------------------------------
// Single kernel, 3 phases, 256 blocks x 256 threads, __launch_bounds__(256,2):
// 2 blocks/SM guaranteed => 296 resident slots >= 256 blocks (barrier-safe),
// and the dots phase keeps the same warps/SM as the standalone version.
//   P1 dots: 64 rows/block (2 passes x 8 warps x 4 rows), raw-w dots scaled
//            by 1/||w_r|| at store; sc kept in smem (block-local).
//   P2 tab:  blockIdx>>1 = (b,r) table, blockIdx&1 = node half. 32 nodes/blk,
//            c(a_n) = sum e^{a_n v_t} v_t / sum e^{a_n v_t} (shift-exact).
//   P3 attn: Catmull-Rom interp of c(a) per (r,s) + out tile [32s][512d].
// Grid barriers: threadfence + monotonic atomic ticket (replay-safe).
// ---------------------------------------------------------------------------
__global__ __launch_bounds__(256, 2) void k_all(const float* __restrict__ src,
                                                const float* __restrict__ tar,
                                                const float* __restrict__ src_mask,
                                                const float* __restrict__ tar_mask,
                                                const float* __restrict__ w,
                                                float* __restrict__ out) {
    __shared__ __align__(16) float shA[Rr * Tt];  // 16 KB: w (P1) / v-row (P2) / v-tile (P3 slow)
    __shared__ float  sc_s[Rr];
    __shared__ float  tab_s[Rr * NNODE];          // 2 KB
    __shared__ float2 meta_s[Rr];
    __shared__ float  tm_s[Tt];                   // 2 KB
    __shared__ float  a_s[Rr * 32];               // 1 KB
    __shared__ float  sm_s[32];
    __shared__ float  c_s[32 * Rr];               // 1 KB
    __shared__ float  red[4][8];
    __shared__ float  s_amin, s_amax, s_vmin, s_vmax;
    __shared__ int    red_one[8];

    int tid  = threadIdx.x;
    int warp = tid >> 5;
    int lane = tid & 31;

    // ================= Phase 1: dots =================
    {
        float4* wn_s = (float4*)shA;
#pragma unroll
        for (int i = 0; i < 4; i++)
            wn_s[tid + 256 * i] = ((const float4*)w)[tid + 256 * i];
        __syncthreads();

        {
            float ss = 0.f;
#pragma unroll
            for (int k = 0; k < 4; k++) {
                float4 x = wn_s[warp * 128 + lane + 32 * k];
                ss += x.x * x.x + x.y * x.y + x.z * x.z + x.w * x.w;
            }
#pragma unroll
            for (int off = 16; off; off >>= 1)
                ss += __shfl_xor_sync(0xffffffffu, ss, off);
            if (lane == 0) sc_s[warp] = 1.0f / fmaxf(sqrtf(ss), 1e-12f);
        }
        __syncthreads();

#pragma unroll
        for (int pass = 0; pass < 2; pass++) {
            int base = blockIdx.x * 64 + pass * 32 + warp * 4;
            bool is_src = base < Bb * Ss;          // 8192 % 64 == 0: no straddle
            const float* eb = is_src ? src : tar;
            int lbase = is_src ? base : base - Bb * Ss;

            u64 acc2[4][Rr];
#pragma unroll
            for (int rr = 0; rr < 4; rr++)
#pragma unroll
                for (int r = 0; r < Rr; r++) acc2[rr][r] = 0ull;

            float4 xa[4], xb[4];
#pragma unroll
            for (int rr = 0; rr < 4; rr++)
                xa[rr] = ((const float4*)(eb + (size_t)(lbase + rr) * Dd))[lane];

#pragma unroll
            for (int k = 0; k < 4; k++) {
                if (k < 3) {
#pragma unroll
                    for (int rr = 0; rr < 4; rr++)
                        xb[rr] = ((const float4*)(eb + (size_t)(lbase + rr) * Dd))[lane + 32 * (k + 1)];
                }
                u64 xp01[4], xp23[4];
#pragma unroll
                for (int rr = 0; rr < 4; rr++) {
                    xp01[rr] = pk(xa[rr].x, xa[rr].y);
                    xp23[rr] = pk(xa[rr].z, xa[rr].w);
                }
#pragma unroll
                for (int r = 0; r < Rr; r++) {
                    float4 wv = wn_s[r * 128 + lane + 32 * k];
                    u64 w01 = pk(wv.x, wv.y);
                    u64 w23 = pk(wv.z, wv.w);
#pragma unroll
                    for (int rr = 0; rr < 4; rr++) {
                        acc2[rr][r] = ffma2(xp01[rr], w01, acc2[rr][r]);
                        acc2[rr][r] = ffma2(xp23[rr], w23, acc2[rr][r]);
                    }
                }
#pragma unroll
                for (int rr = 0; rr < 4; rr++) xa[rr] = xb[rr];
            }

            float t[32];
#pragma unroll
            for (int rr = 0; rr < 4; rr++)
#pragma unroll
                for (int r = 0; r < Rr; r++) {
                    float lo, hi;
                    upk(acc2[rr][r], lo, hi);
                    t[rr * 8 + r] = lo + hi;
                }

#pragma unroll
            for (int st = 0; st < 5; st++) {
                int off = 1 << st;
                int sel = lane & off;
#pragma unroll
                for (int jj = 0; jj < (16 >> st); jj++) {
                    float give = sel ? t[2 * jj]     : t[2 * jj + 1];
                    float keep = sel ? t[2 * jj + 1] : t[2 * jj];
                    float recv = __shfl_xor_sync(0xffffffffu, give, off);
                    t[jj] = keep + recv;
                }
            }

            {
                int rr = lane >> 3, r = lane & 7;
                int gid = lbase + rr;
                int bb = gid >> 9, s = gid & 511;
                float* gw = is_src ? g_src_wt : g_tar_wt;
                gw[((size_t)bb * Rr + r) * Ss + s] = t[0] * sc_s[r];
            }
        }
    }

    // ================= Grid barrier 1 =================
    __syncthreads();
    __threadfence();
    if (tid == 0) {
        unsigned ticket = atomicAdd(&g_bar, 1u);
        unsigned target = (ticket / NBLK + 1u) * NBLK;
        while (*(volatile unsigned*)&g_bar < target) { }
    }
    __syncthreads();

    // ================= Phase 2: c(a) tables (2 blocks per table) ===========
    {
        int br    = blockIdx.x >> 1;
        int nhalf = blockIdx.x & 1;

        float a0 = g_src_wt[(size_t)br * Ss + tid];
        float a1 = g_src_wt[(size_t)br * Ss + 256 + tid];
        float v0 = g_tar_wt[(size_t)br * Tt + tid];
        float v1 = g_tar_wt[(size_t)br * Tt + 256 + tid];
        shA[tid]       = v0;
        shA[tid + 256] = v1;

        float amn = fminf(a0, a1), amx = fmaxf(a0, a1);
        float vmn = fminf(v0, v1), vmx = fmaxf(v0, v1);
#pragma unroll
        for (int off = 16; off; off >>= 1) {
            amn = fminf(amn, __shfl_xor_sync(0xffffffffu, amn, off));
            amx = fmaxf(amx, __shfl_xor_sync(0xffffffffu, amx, off));
            vmn = fminf(vmn, __shfl_xor_sync(0xffffffffu, vmn, off));
            vmx = fmaxf(vmx, __shfl_xor_sync(0xffffffffu, vmx, off));
        }
        if (lane == 0) {
            red[0][warp] = amn; red[1][warp] = amx;
            red[2][warp] = vmn; red[3][warp] = vmx;
        }
        __syncthreads();
        if (warp == 0) {
            int li = lane & 7;
            float t0 = red[0][li], t1 = red[1][li], t2 = red[2][li], t3 = red[3][li];
#pragma unroll
            for (int off = 4; off; off >>= 1) {
                t0 = fminf(t0, __shfl_xor_sync(0xffffffffu, t0, off));
                t1 = fmaxf(t1, __shfl_xor_sync(0xffffffffu, t1, off));
                t2 = fminf(t2, __shfl_xor_sync(0xffffffffu, t2, off));
                t3 = fmaxf(t3, __shfl_xor_sync(0xffffffffu, t3, off));
            }
            if (lane == 0) { s_amin = t0; s_amax = t1; s_vmin = t2; s_vmax = t3; }
        }
        __syncthreads();

        float h  = (s_amax - s_amin) * (1.0f / 59.0f) + 1e-20f;
        float g0 = s_amin - 2.0f * h;

        int node = nhalf * 32 + (tid >> 3);
        int sub  = tid & 7;
        float an   = fmaf((float)node, h, g0);
        float vref = (an >= 0.f) ? s_vmax : s_vmin;
        float a2   = an * LOG2E;
        float nm2  = -a2 * vref;            // x = a2*(v - vref) <= 0

        float S0 = 0.f, S1 = 0.f, A0 = 0.f, A1 = 0.f;
#pragma unroll 8
        for (int i = 0; i < 64; i += 2) {
            float va = shA[8 * i + sub];
            float vb = shA[8 * (i + 1) + sub];
            float ea = ex2(fmaf(a2, va, nm2));
            float eb = ex2(fmaf(a2, vb, nm2));
            S0 += ea; S1 += eb;
            A0 = fmaf(ea, va, A0);
            A1 = fmaf(eb, vb, A1);
        }
        float S = S0 + S1, A = A0 + A1;
        S += __shfl_xor_sync(0xffffffffu, S, 1);
        A += __shfl_xor_sync(0xffffffffu, A, 1);
        S += __shfl_xor_sync(0xffffffffu, S, 2);
        A += __shfl_xor_sync(0xffffffffu, A, 2);
        S += __shfl_xor_sync(0xffffffffu, S, 4);
        A += __shfl_xor_sync(0xffffffffu, A, 4);

        if (sub == 0) g_tab[(size_t)br * NNODE + node] = A / S;
        if (tid == 0) g_meta[br] = make_float2(g0, 1.0f / h);
    }

    // ================= Grid barrier 2 =================
    __syncthreads();
    __threadfence();
    if (tid == 0) {
        unsigned ticket = atomicAdd(&g_bar, 1u);
        unsigned target = (ticket / NBLK + 1u) * NBLK;
        while (*(volatile unsigned*)&g_bar < target) { }
    }
    __syncthreads();

    // ================= Phase 3: attention (interp) + output ================
    int b  = blockIdx.x >> 4;
    int s0 = (blockIdx.x & 15) * 32;
    int r  = tid >> 5;         // 0..7
    int j  = tid & 31;

    tab_s[tid]       = g_tab[(size_t)b * Rr * NNODE + tid];
    tab_s[tid + 256] = g_tab[(size_t)b * Rr * NNODE + tid + 256];
    if (tid < Rr) meta_s[tid] = g_meta[b * Rr + tid];

    float4 tm4 = make_float4(1.f, 1.f, 1.f, 1.f);
    if (tid < 128) {
        tm4 = ((const float4*)(tar_mask + (size_t)b * Tt))[tid];
        ((float4*)tm_s)[tid] = tm4;
    }
    a_s[tid] = g_src_wt[((size_t)b * Rr + r) * Ss + s0 + j];
    float smv = 1.f;
    if (tid < 32) { smv = src_mask[(size_t)b * Ss + s0 + tid]; sm_s[tid] = smv; }

    {
        int ok = 1;
        if (tid < 128) ok = (tm4.x == 1.0f) & (tm4.y == 1.0f) & (tm4.z == 1.0f) & (tm4.w == 1.0f);
        if (tid < 32)  ok &= (smv == 1.0f);
        unsigned bal = __ballot_sync(0xffffffffu, ok);
        if (lane == 0) red_one[warp] = (bal == 0xffffffffu);
    }
    __syncthreads();

    int fast = red_one[0] & red_one[1] & red_one[2] & red_one[3]
             & red_one[4] & red_one[5] & red_one[6] & red_one[7];

    if (fast) {
        float a = a_s[tid];
        float2 mt = meta_s[r];
        float u = (a - mt.x) * mt.y;
        u = fminf(fmaxf(u, 2.0f), 61.0f);
        int k = (int)u;
        float f = u - (float)k;
        const float* tp = tab_s + r * NNODE + k;
        float p0 = tp[-1], p1 = tp[0], p2 = tp[1], p3 = tp[2];
        float c = p1 + 0.5f * f * ((p2 - p0)
                + f * ((2.f * p0 - 5.f * p1 + 4.f * p2 - p3)
                + f * (3.f * (p1 - p2) + p3 - p0)));
        c_s[j * Rr + r] = c;
        __syncthreads();
    } else {
        // slow path: load v tile, per-thread full-T two-pass softmax
        const float4* vsrc = (const float4*)(g_tar_wt + (size_t)b * Rr * Tt);
#pragma unroll
        for (int i = 0; i < 4; i++)
            ((float4*)shA)[tid + 256 * i] = vsrc[tid + 256 * i];
        __syncthreads();

        const float4* vv = (const float4*)(shA + r * Tt);
        const float4* tt = (const float4*)tm_s;
        float a  = a_s[tid];
        float sm = sm_s[j];
        float m = -3.4e38f;
#pragma unroll 4
        for (int t4 = 0; t4 < 128; t4++) {
            float4 v = vv[t4], tm = tt[t4];
            float x0 = fmaf(a, v.x, fmaf(sm * tm.x, 1e10f, NEG_BIG));
            float x1 = fmaf(a, v.y, fmaf(sm * tm.y, 1e10f, NEG_BIG));
            float x2 = fmaf(a, v.z, fmaf(sm * tm.z, 1e10f, NEG_BIG));
            float x3 = fmaf(a, v.w, fmaf(sm * tm.w, 1e10f, NEG_BIG));
            m = fmaxf(m, fmaxf(fmaxf(x0, x1), fmaxf(x2, x3)));
        }
        float S = 0.f, A = 0.f;
#pragma unroll 4
        for (int t4 = 0; t4 < 128; t4++) {
            float4 v = vv[t4], tm = tt[t4];
            float x0 = fmaf(a, v.x, fmaf(sm * tm.x, 1e10f, NEG_BIG));
            float x1 = fmaf(a, v.y, fmaf(sm * tm.y, 1e10f, NEG_BIG));
            float x2 = fmaf(a, v.z, fmaf(sm * tm.z, 1e10f, NEG_BIG));
            float x3 = fmaf(a, v.w, fmaf(sm * tm.w, 1e10f, NEG_BIG));
            float e0 = ex2((x0 - m) * LOG2E);
            float e1 = ex2((x1 - m) * LOG2E);
            float e2 = ex2((x2 - m) * LOG2E);
            float e3 = ex2((x3 - m) * LOG2E);
            S += e0 + e1 + e2 + e3;
            A = fmaf(e0, v.x, A);
            A = fmaf(e1, v.y, A);
            A = fmaf(e2, v.z, A);
            A = fmaf(e3, v.w, A);
        }
        c_s[j * Rr + r] = A / S;
        __syncthreads();
    }

    // out tile [32 s][512 d] = c . (w * sc)
    {
        int d4 = tid & 127;
        int jg = tid >> 7;   // 0..1
        float4 wv[Rr];
#pragma unroll
        for (int rr = 0; rr < Rr; rr++) {
            float4 ww = ((const float4*)w)[rr * 128 + d4];
            float sc = sc_s[rr];
            ww.x *= sc; ww.y *= sc; ww.z *= sc; ww.w *= sc;
            wv[rr] = ww;
        }

        float4* out4 = (float4*)out;
#pragma unroll
        for (int k = 0; k < 16; k++) {
            int jj = jg + 2 * k;
            float4 o = make_float4(0.f, 0.f, 0.f, 0.f);
#pragma unroll
            for (int rr = 0; rr < Rr; rr++) {
                float c = c_s[jj * Rr + rr];
                o.x = fmaf(c, wv[rr].x, o.x);
                o.y = fmaf(c, wv[rr].y, o.y);
                o.z = fmaf(c, wv[rr].z, o.z);
                o.w = fmaf(c, wv[rr].w, o.w);
            }
            out4[((size_t)b * Ss + s0 + jj) * (Dd / 4) + d4] = o;
        }
    }
}

// ---------------------------------------------------------------------------
extern "C" void kernel_launch(void* const* d_in, const int* in_sizes, int n_in,
                              void* d_out, int out_size) {
    const float* src_emb  = (const float*)d_in[0];
    const float* tar_emb  = (const float*)d_in[1];
    const float* src_mask = (const float*)d_in[2];
    const float* tar_mask = (const float*)d_in[3];
    const float* w        = (const float*)d_in[4];
    float* out            = (float*)d_out;

    k_all<<<NBLK, 256>>>(src_emb, tar_emb, src_mask, tar_mask, w, out);
}

// round 17
// speedup vs baseline: 1.2301x; 1.2301x over previous
#include <cuda_runtime.h>
#include <math.h>

#define Bb 16
#define Ss 512
#define Tt 512
#define Dd 512
#define Rr 8
#define NEG_BIG (-1e10f)
#define LOG2E 1.4426950408889634f
#define NNODE 64
#define NBLK2 256

typedef unsigned long long u64;

// scratch (device globals; no allocation allowed)
__device__ float    g_sc[Rr];                  // 1/||w_r||
__device__ float    g_src_wt[Bb * Rr * Ss];    // [b,r,s]
__device__ float    g_tar_wt[Bb * Rr * Tt];    // [b,r,t]
__device__ float    g_tab[Bb * Rr * NNODE];    // c(a) tables
__device__ float2   g_meta[Bb * Rr];           // (g0, 1/h) per (b,r)
__device__ unsigned g_bar = 0;                 // monotonic grid-barrier ticket

__device__ __forceinline__ float ex2(float x) {
    float y;
    asm("ex2.approx.f32 %0, %1;" : "=f"(y) : "f"(x));
    return y;
}
__device__ __forceinline__ u64 pk(float lo, float hi) {
    u64 d; asm("mov.b64 %0, {%1, %2};" : "=l"(d) : "f"(lo), "f"(hi)); return d;
}
__device__ __forceinline__ void upk(u64 p, float& lo, float& hi) {
    asm("mov.b64 {%0, %1}, %2;" : "=f"(lo), "=f"(hi) : "l"(p));
}
__device__ __forceinline__ u64 ffma2(u64 a, u64 b, u64 c) {
    u64 d; asm("fma.rn.f32x2 %0, %1, %2, %3;" : "=l"(d) : "l"(a), "l"(b), "l"(c)); return d;
}

// ---------------------------------------------------------------------------
// Kernel 1 (unchanged, proven): dots of every embedding row with all 8 raw w
// rows; scaled by 1/||w_r|| at the store. 512 blocks x 32 rows, 256 threads.
// ---------------------------------------------------------------------------
__global__ __launch_bounds__(256, 2) void k_dots(const float* __restrict__ src,
                                                 const float* __restrict__ tar,
                                                 const float* __restrict__ w) {
    __shared__ float4 wn_s[Rr * Dd / 4];  // 16 KB raw w
    __shared__ float  sc_s[Rr];
    int tid  = threadIdx.x;
    int warp = tid >> 5;
    int lane = tid & 31;

    int base = blockIdx.x * 32 + warp * 4;
    bool is_src = base < Bb * Ss;            // blocks never straddle (8192 % 32 == 0)
    const float* eb = is_src ? src : tar;
    int lbase = is_src ? base : base - Bb * Ss;

    float4 xa[4], xb[4];
#pragma unroll
    for (int rr = 0; rr < 4; rr++)
        xa[rr] = ((const float4*)(eb + (size_t)(lbase + rr) * Dd))[lane];

#pragma unroll
    for (int i = 0; i < 4; i++)
        wn_s[tid + 256 * i] = ((const float4*)w)[tid + 256 * i];
    __syncthreads();

    {
        float ss = 0.f;
#pragma unroll
        for (int k = 0; k < 4; k++) {
            float4 x = wn_s[warp * 128 + lane + 32 * k];
            ss += x.x * x.x + x.y * x.y + x.z * x.z + x.w * x.w;
        }
#pragma unroll
        for (int off = 16; off; off >>= 1)
            ss += __shfl_xor_sync(0xffffffffu, ss, off);
        if (lane == 0) {
            float sc = 1.0f / fmaxf(sqrtf(ss), 1e-12f);
            sc_s[warp] = sc;
            if (blockIdx.x == 0) g_sc[warp] = sc;
        }
    }
    __syncthreads();

    u64 acc2[4][Rr];
#pragma unroll
    for (int rr = 0; rr < 4; rr++)
#pragma unroll
        for (int r = 0; r < Rr; r++) acc2[rr][r] = 0ull;

#pragma unroll
    for (int k = 0; k < 4; k++) {
        if (k < 3) {
#pragma unroll
            for (int rr = 0; rr < 4; rr++)
                xb[rr] = ((const float4*)(eb + (size_t)(lbase + rr) * Dd))[lane + 32 * (k + 1)];
        }
        u64 xp01[4], xp23[4];
#pragma unroll
        for (int rr = 0; rr < 4; rr++) {
            xp01[rr] = pk(xa[rr].x, xa[rr].y);
            xp23[rr] = pk(xa[rr].z, xa[rr].w);
        }
#pragma unroll
        for (int r = 0; r < Rr; r++) {
            float4 wv = wn_s[r * 128 + lane + 32 * k];
            u64 w01 = pk(wv.x, wv.y);
            u64 w23 = pk(wv.z, wv.w);
#pragma unroll
            for (int rr = 0; rr < 4; rr++) {
                acc2[rr][r] = ffma2(xp01[rr], w01, acc2[rr][r]);
                acc2[rr][r] = ffma2(xp23[rr], w23, acc2[rr][r]);
            }
        }
#pragma unroll
        for (int rr = 0; rr < 4; rr++) xa[rr] = xb[rr];
    }

    float t[32];
#pragma unroll
    for (int rr = 0; rr < 4; rr++)
#pragma unroll
        for (int r = 0; r < Rr; r++) {
            float lo, hi;
            upk(acc2[rr][r], lo, hi);
            t[rr * 8 + r] = lo + hi;
        }

#pragma unroll
    for (int st = 0; st < 5; st++) {
        int off = 1 << st;
        int sel = lane & off;
#pragma unroll
        for (int j = 0; j < (16 >> st); j++) {
            float give = sel ? t[2 * j]     : t[2 * j + 1];
            float keep = sel ? t[2 * j + 1] : t[2 * j];
            float recv = __shfl_xor_sync(0xffffffffu, give, off);
            t[j] = keep + recv;
        }
    }

    {
        int rr = lane >> 3, r = lane & 7;
        int gid = lbase + rr;
        int bb = gid >> 9, s = gid & 511;
        float* gw = is_src ? g_src_wt : g_tar_wt;
        gw[((size_t)bb * Rr + r) * Ss + s] = t[0] * sc_s[r];
    }
}

// ---------------------------------------------------------------------------
// Kernel 2 (fused tab + attn + out): 256 blocks x 256 threads,
// __launch_bounds__(256,2): 296 resident slots >= 256 blocks — barrier-safe.
// Phase A (tab): blockIdx>>1 = (b,r), blockIdx&1 = node half; 32 nodes/block,
//   c(a_n) = sum_t e^{a_n v_t} v_t / sum_t e^{a_n v_t}  (shift-exact).
// Ticket grid barrier (monotonic, replay-safe).
// Phase B (attn+out): blockIdx = b*16 + s-tile. Fast path: Catmull-Rom
//   interp of c(a) (no v-tile load). Slow masked path: per-thread full-T
//   two-pass fp32 softmax. Then out tile [32 s][512 d] = c · (w * g_sc).
// ---------------------------------------------------------------------------
__global__ __launch_bounds__(256, 2) void k_tab_attn(const float* __restrict__ src_mask,
                                                     const float* __restrict__ tar_mask,
                                                     const float* __restrict__ w,
                                                     float* __restrict__ out) {
    __shared__ __align__(16) float shA[Rr * Tt];  // 16 KB: v-row (A) / v-tile (B slow)
    __shared__ float  tab_s[Rr * NNODE];          // 2 KB
    __shared__ float2 meta_s[Rr];
    __shared__ float  tm_s[Tt];                   // 2 KB
    __shared__ float  a_s[Rr * 32];               // 1 KB
    __shared__ float  sm_s[32];
    __shared__ float  c_s[32 * Rr];               // 1 KB
    __shared__ float  red[4][8];
    __shared__ float  s_amin, s_amax, s_vmin, s_vmax;
    __shared__ int    red_one[8];

    int tid  = threadIdx.x;
    int warp = tid >> 5;
    int lane = tid & 31;

    // ================= Phase A: c(a) tables (2 blocks per table) ===========
    {
        int br    = blockIdx.x >> 1;
        int nhalf = blockIdx.x & 1;

        float a0 = g_src_wt[(size_t)br * Ss + tid];
        float a1 = g_src_wt[(size_t)br * Ss + 256 + tid];
        float v0 = g_tar_wt[(size_t)br * Tt + tid];
        float v1 = g_tar_wt[(size_t)br * Tt + 256 + tid];
        shA[tid]       = v0;
        shA[tid + 256] = v1;

        float amn = fminf(a0, a1), amx = fmaxf(a0, a1);
        float vmn = fminf(v0, v1), vmx = fmaxf(v0, v1);
#pragma unroll
        for (int off = 16; off; off >>= 1) {
            amn = fminf(amn, __shfl_xor_sync(0xffffffffu, amn, off));
            amx = fmaxf(amx, __shfl_xor_sync(0xffffffffu, amx, off));
            vmn = fminf(vmn, __shfl_xor_sync(0xffffffffu, vmn, off));
            vmx = fmaxf(vmx, __shfl_xor_sync(0xffffffffu, vmx, off));
        }
        if (lane == 0) {
            red[0][warp] = amn; red[1][warp] = amx;
            red[2][warp] = vmn; red[3][warp] = vmx;
        }
        __syncthreads();
        if (warp == 0) {
            int li = lane & 7;
            float t0 = red[0][li], t1 = red[1][li], t2 = red[2][li], t3 = red[3][li];
#pragma unroll
            for (int off = 4; off; off >>= 1) {
                t0 = fminf(t0, __shfl_xor_sync(0xffffffffu, t0, off));
                t1 = fmaxf(t1, __shfl_xor_sync(0xffffffffu, t1, off));
                t2 = fminf(t2, __shfl_xor_sync(0xffffffffu, t2, off));
                t3 = fmaxf(t3, __shfl_xor_sync(0xffffffffu, t3, off));
            }
            if (lane == 0) { s_amin = t0; s_amax = t1; s_vmin = t2; s_vmax = t3; }
        }
        __syncthreads();

        float h  = (s_amax - s_amin) * (1.0f / 59.0f) + 1e-20f;
        float g0 = s_amin - 2.0f * h;

        int node = nhalf * 32 + (tid >> 3);
        int sub  = tid & 7;
        float an   = fmaf((float)node, h, g0);
        float vref = (an >= 0.f) ? s_vmax : s_vmin;
        float a2   = an * LOG2E;
        float nm2  = -a2 * vref;            // x = a2*(v - vref) <= 0

        float S0 = 0.f, S1 = 0.f, A0 = 0.f, A1 = 0.f;
#pragma unroll 8
        for (int i = 0; i < 64; i += 2) {
            float va = shA[8 * i + sub];
            float vb = shA[8 * (i + 1) + sub];
            float ea = ex2(fmaf(a2, va, nm2));
            float eb = ex2(fmaf(a2, vb, nm2));
            S0 += ea; S1 += eb;
            A0 = fmaf(ea, va, A0);
            A1 = fmaf(eb, vb, A1);
        }
        float S = S0 + S1, A = A0 + A1;
        S += __shfl_xor_sync(0xffffffffu, S, 1);
        A += __shfl_xor_sync(0xffffffffu, A, 1);
        S += __shfl_xor_sync(0xffffffffu, S, 2);
        A += __shfl_xor_sync(0xffffffffu, A, 2);
        S += __shfl_xor_sync(0xffffffffu, S, 4);
        A += __shfl_xor_sync(0xffffffffu, A, 4);

        if (sub == 0) g_tab[(size_t)br * NNODE + node] = A / S;
        if (tid == 0 && nhalf == 0) g_meta[br] = make_float2(g0, 1.0f / h);
    }

    // ================= Grid barrier =================
    __syncthreads();
    __threadfence();
    if (tid == 0) {
        unsigned ticket = atomicAdd(&g_bar, 1u);
        unsigned target = (ticket / NBLK2 + 1u) * NBLK2;
        while (*(volatile unsigned*)&g_bar < target) { }
    }
    __syncthreads();

    // ================= Phase B: attention (interp) + output ================
    int b  = blockIdx.x >> 4;
    int s0 = (blockIdx.x & 15) * 32;
    int r  = tid >> 5;         // 0..7
    int j  = tid & 31;

    tab_s[tid]       = g_tab[(size_t)b * Rr * NNODE + tid];
    tab_s[tid + 256] = g_tab[(size_t)b * Rr * NNODE + tid + 256];
    if (tid < Rr) meta_s[tid] = g_meta[b * Rr + tid];

    float4 tm4 = make_float4(1.f, 1.f, 1.f, 1.f);
    if (tid < 128) {
        tm4 = ((const float4*)(tar_mask + (size_t)b * Tt))[tid];
        ((float4*)tm_s)[tid] = tm4;
    }
    a_s[tid] = g_src_wt[((size_t)b * Rr + r) * Ss + s0 + j];
    float smv = 1.f;
    if (tid < 32) { smv = src_mask[(size_t)b * Ss + s0 + tid]; sm_s[tid] = smv; }

    {
        int ok = 1;
        if (tid < 128) ok = (tm4.x == 1.0f) & (tm4.y == 1.0f) & (tm4.z == 1.0f) & (tm4.w == 1.0f);
        if (tid < 32)  ok &= (smv == 1.0f);
        unsigned bal = __ballot_sync(0xffffffffu, ok);
        if (lane == 0) red_one[warp] = (bal == 0xffffffffu);
    }
    __syncthreads();

    int fast = red_one[0] & red_one[1] & red_one[2] & red_one[3]
             & red_one[4] & red_one[5] & red_one[6] & red_one[7];

    if (fast) {
        float a = a_s[tid];
        float2 mt = meta_s[r];
        float u = (a - mt.x) * mt.y;
        u = fminf(fmaxf(u, 2.0f), 61.0f);
        int k = (int)u;
        float f = u - (float)k;
        const float* tp = tab_s + r * NNODE + k;
        float p0 = tp[-1], p1 = tp[0], p2 = tp[1], p3 = tp[2];
        float c = p1 + 0.5f * f * ((p2 - p0)
                + f * ((2.f * p0 - 5.f * p1 + 4.f * p2 - p3)
                + f * (3.f * (p1 - p2) + p3 - p0)));
        c_s[j * Rr + r] = c;
        __syncthreads();
    } else {
        // slow path: load v tile, per-thread full-T two-pass softmax
        const float4* vsrc = (const float4*)(g_tar_wt + (size_t)b * Rr * Tt);
#pragma unroll
        for (int i = 0; i < 4; i++)
            ((float4*)shA)[tid + 256 * i] = vsrc[tid + 256 * i];
        __syncthreads();

        const float4* vv = (const float4*)(shA + r * Tt);
        const float4* tt = (const float4*)tm_s;
        float a  = a_s[tid];
        float sm = sm_s[j];
        float m = -3.4e38f;
#pragma unroll 4
        for (int t4 = 0; t4 < 128; t4++) {
            float4 v = vv[t4], tm = tt[t4];
            float x0 = fmaf(a, v.x, fmaf(sm * tm.x, 1e10f, NEG_BIG));
            float x1 = fmaf(a, v.y, fmaf(sm * tm.y, 1e10f, NEG_BIG));
            float x2 = fmaf(a, v.z, fmaf(sm * tm.z, 1e10f, NEG_BIG));
            float x3 = fmaf(a, v.w, fmaf(sm * tm.w, 1e10f, NEG_BIG));
            m = fmaxf(m, fmaxf(fmaxf(x0, x1), fmaxf(x2, x3)));
        }
        float S = 0.f, A = 0.f;
#pragma unroll 4
        for (int t4 = 0; t4 < 128; t4++) {
            float4 v = vv[t4], tm = tt[t4];
            float x0 = fmaf(a, v.x, fmaf(sm * tm.x, 1e10f, NEG_BIG));
            float x1 = fmaf(a, v.y, fmaf(sm * tm.y, 1e10f, NEG_BIG));
            float x2 = fmaf(a, v.z, fmaf(sm * tm.z, 1e10f, NEG_BIG));
            float x3 = fmaf(a, v.w, fmaf(sm * tm.w, 1e10f, NEG_BIG));
            float e0 = ex2((x0 - m) * LOG2E);
            float e1 = ex2((x1 - m) * LOG2E);
            float e2 = ex2((x2 - m) * LOG2E);
            float e3 = ex2((x3 - m) * LOG2E);
            S += e0 + e1 + e2 + e3;
            A = fmaf(e0, v.x, A);
            A = fmaf(e1, v.y, A);
            A = fmaf(e2, v.z, A);
            A = fmaf(e3, v.w, A);
        }
        c_s[j * Rr + r] = A / S;
        __syncthreads();
    }

    // out tile [32 s][512 d] = c . (w * g_sc)
    {
        int d4 = tid & 127;
        int jg = tid >> 7;   // 0..1
        float4 wv[Rr];
#pragma unroll
        for (int rr = 0; rr < Rr; rr++) {
            float4 ww = ((const float4*)w)[rr * 128 + d4];
            float sc = g_sc[rr];
            ww.x *= sc; ww.y *= sc; ww.z *= sc; ww.w *= sc;
            wv[rr] = ww;
        }

        float4* out4 = (float4*)out;
#pragma unroll
        for (int k = 0; k < 16; k++) {
            int jj = jg + 2 * k;
            float4 o = make_float4(0.f, 0.f, 0.f, 0.f);
#pragma unroll
            for (int rr = 0; rr < Rr; rr++) {
                float c = c_s[jj * Rr + rr];
                o.x = fmaf(c, wv[rr].x, o.x);
                o.y = fmaf(c, wv[rr].y, o.y);
                o.z = fmaf(c, wv[rr].z, o.z);
                o.w = fmaf(c, wv[rr].w, o.w);
            }
            out4[((size_t)b * Ss + s0 + jj) * (Dd / 4) + d4] = o;
        }
    }
}

// ---------------------------------------------------------------------------
extern "C" void kernel_launch(void* const* d_in, const int* in_sizes, int n_in,
                              void* d_out, int out_size) {
    const float* src_emb  = (const float*)d_in[0];
    const float* tar_emb  = (const float*)d_in[1];
    const float* src_mask = (const float*)d_in[2];
    const float* tar_mask = (const float*)d_in[3];
    const float* w        = (const float*)d_in[4];
    float* out            = (float*)d_out;

    k_dots<<<(Bb * Ss + Bb * Tt) / 32, 256>>>(src_emb, tar_emb, w);
    k_tab_attn<<<NBLK2, 256>>>(src_mask, tar_mask, w, out);
}